// round 8
// baseline (speedup 1.0000x reference)
#include <cuda_runtime.h>
#include <cuda_fp16.h>
#include <cstdint>

#define BB  2
#define NN  2048
#define DM  1024
#define HH  16
#define DK  64
#define TBB 16

// ---------------------------------------------------------------------------
// Device scratch (static; no allocation)
// ---------------------------------------------------------------------------
__device__ int    g_flags[BB * TBB * TBB];       // 0=skip, 1=full, 2=partial
__device__ __half g_qh[(size_t)BB * NN * DM];    // Q fp16, same layout as input
__device__ __half g_kh[(size_t)BB * NN * DM];    // K fp16, same layout
__device__ __half g_vt[(size_t)BB * HH * DK * NN]; // V fp16 transposed [b][h][d][n]

// ---------------------------------------------------------------------------
// Prepass 1: convert Q and K to fp16 (layout-preserving)
// ---------------------------------------------------------------------------
__global__ void __launch_bounds__(256) convert_qk_kernel(const float* __restrict__ q,
                                                         const float* __restrict__ k) {
    const size_t total = (size_t)BB * NN * DM / 2;
    __half2* qo = reinterpret_cast<__half2*>(g_qh);
    __half2* ko = reinterpret_cast<__half2*>(g_kh);
    const float2* qi = reinterpret_cast<const float2*>(q);
    const float2* ki = reinterpret_cast<const float2*>(k);
    for (size_t i = (size_t)blockIdx.x * blockDim.x + threadIdx.x; i < total;
         i += (size_t)gridDim.x * blockDim.x) {
        float2 fq = qi[i];
        qo[i] = __floats2half2_rn(fq.x, fq.y);
        float2 fk = ki[i];
        ko[i] = __floats2half2_rn(fk.x, fk.y);
    }
}

// ---------------------------------------------------------------------------
// Prepass 2: V -> fp16 transposed per head: g_vt[b][h][d][n] = V[b][n][h*64+d]
// Block (32,32): coalesced f32 reads (consecutive d), coalesced fp16 writes
// (consecutive n). Float staging tile avoids smem bank conflicts both ways.
// ---------------------------------------------------------------------------
__global__ void __launch_bounds__(1024) vtrans_kernel(const float* __restrict__ v) {
    __shared__ float tile[32][33];
    const int tx = threadIdx.x, ty = threadIdx.y;
    const int n0 = blockIdx.x * 32;
    const int h  = blockIdx.y >> 1;
    const int d0 = (blockIdx.y & 1) * 32;
    const int b  = blockIdx.z;
    tile[tx][ty] = v[((size_t)(b * NN + n0 + ty)) * DM + h * DK + d0 + tx];
    __syncthreads();
    g_vt[((size_t)((b * HH + h) * DK + d0 + ty)) * NN + n0 + tx] =
        __float2half_rn(tile[ty][tx]);
}

// ---------------------------------------------------------------------------
// Prepass 3: compress token mask x block-sparse mask into per-tile flags.
// Reads the 33.5MB mask exactly once; hot loop then never touches it
// (mask is all-ones in this dataset -> flags are 0/1 only).
// ---------------------------------------------------------------------------
__global__ void __launch_bounds__(256) prepass_kernel(const int* __restrict__ mask,
                                                      const int* __restrict__ bsm) {
    int kb = blockIdx.x, qb = blockIdx.y, b = blockIdx.z;
    int t = threadIdx.x;
    int allv = 1, anyv = 0;
    const int* base = mask + ((size_t)b * NN + (size_t)qb * 128) * NN + (size_t)kb * 128;
    for (int i = t; i < 128 * 128; i += 256) {
        int r = i >> 7, c = i & 127;
        int nz = (base[(size_t)r * NN + c] != 0);
        allv &= nz;
        anyv |= nz;
    }
    for (int off = 16; off; off >>= 1) {
        allv &= __shfl_xor_sync(0xffffffffu, allv, off);
        anyv |= __shfl_xor_sync(0xffffffffu, anyv, off);
    }
    __shared__ int s_all[8], s_any[8];
    int w = t >> 5;
    if ((t & 31) == 0) { s_all[w] = allv; s_any[w] = anyv; }
    __syncthreads();
    if (t == 0) {
        int A = 1, O = 0;
        for (int i = 0; i < 8; i++) { A &= s_all[i]; O |= s_any[i]; }
        int f = 0;
        if (bsm[qb * TBB + kb] != 0 && O) f = A ? 1 : 2;
        g_flags[(b * TBB + qb) * TBB + kb] = f;
    }
}

// ---------------------------------------------------------------------------
// mma.sync m16n8k16 row.col f32.f16.f16.f32
// ---------------------------------------------------------------------------
__device__ __forceinline__ void mma16816(float c[4],
                                         unsigned a0, unsigned a1, unsigned a2, unsigned a3,
                                         unsigned b0, unsigned b1) {
    asm volatile(
        "mma.sync.aligned.m16n8k16.row.col.f32.f16.f16.f32 "
        "{%0,%1,%2,%3}, {%4,%5,%6,%7}, {%8,%9}, {%0,%1,%2,%3};\n"
        : "+f"(c[0]), "+f"(c[1]), "+f"(c[2]), "+f"(c[3])
        : "r"(a0), "r"(a1), "r"(a2), "r"(a3), "r"(b0), "r"(b1));
}

__device__ __forceinline__ unsigned pack_h2(float a, float b) {
    __half2 h = __floats2half2_rn(a, b);
    return *reinterpret_cast<unsigned*>(&h);
}

// ---------------------------------------------------------------------------
// Flash attention over allowed K blocks.
// Grid: (H, TB, B). Block: 256 threads = 8 warps; warp w owns q rows
// [qb*128 + w*16, +16). Each 128-wide K tile is processed as two 64-wide
// online-softmax chunks (hf=0,1) to bound register pressure.
// ---------------------------------------------------------------------------
__global__ void __launch_bounds__(256) attn_kernel(const float* __restrict__ taup,
                                                   const int* __restrict__ mask,
                                                   float* __restrict__ out) {
    __shared__ __half sK[128 * 72];   // K tile [kk][d], stride 72 (also Q staging)
    __shared__ __half sV[64 * 136];   // V tile transposed [d][kk], stride 136

    const int h = blockIdx.x, qb = blockIdx.y, b = blockIdx.z;
    const int tid = threadIdx.x;
    const int w = tid >> 5, lane = tid & 31;
    const int g = lane >> 2, t = lane & 3;

    const float sc = __ldg(taup) * 0.125f;   // tau / sqrt(64)

    // ---- stage Q tile (fp16 scratch) through sK, build A fragments ----
    {
        const size_t qbase = ((size_t)(b * NN + qb * 128)) * DM + h * DK;
#pragma unroll
        for (int p = tid; p < 1024; p += 256) {
            int r = p >> 3, s = p & 7;
            *(uint4*)&sK[r * 72 + s * 8] =
                *(const uint4*)(g_qh + qbase + (size_t)r * DM + s * 8);
        }
    }
    __syncthreads();
    unsigned qa[4][4];
    {
        int r0 = w * 16 + g;
#pragma unroll
        for (int c4 = 0; c4 < 4; c4++) {
            int cb = c4 * 16 + t * 2;
            qa[c4][0] = *(const unsigned*)&sK[r0 * 72 + cb];
            qa[c4][1] = *(const unsigned*)&sK[(r0 + 8) * 72 + cb];
            qa[c4][2] = *(const unsigned*)&sK[r0 * 72 + cb + 8];
            qa[c4][3] = *(const unsigned*)&sK[(r0 + 8) * 72 + cb + 8];
        }
    }
    __syncthreads();

    float oacc[8][4];
#pragma unroll
    for (int j = 0; j < 8; j++) {
        oacc[j][0] = 0.f; oacc[j][1] = 0.f; oacc[j][2] = 0.f; oacc[j][3] = 0.f;
    }
    float m0 = -1e30f, m1 = -1e30f, l0 = 0.f, l1 = 0.f;

    const int frow = (b * TBB + qb) * TBB;
    const size_t kb_stride = (size_t)128 * DM;
    const size_t kbase0 = ((size_t)(b * NN)) * DM + h * DK;
    const size_t vbase0 = ((size_t)((b * HH + h) * DK)) * NN;

    for (int kb = 0; kb < TBB; kb++) {
        const int flag = g_flags[frow + kb];
        if (flag == 0) continue;

        // ---- cooperative fill (pure fp16 uint4 copies, conflict-light) ----
        const size_t kbase = kbase0 + (size_t)kb * kb_stride;
        const size_t vbase = vbase0 + (size_t)kb * 128;
#pragma unroll
        for (int p = tid; p < 1024; p += 256) {
            int r = p >> 3, s = p & 7;
            *(uint4*)&sK[r * 72 + s * 8] =
                *(const uint4*)(g_kh + kbase + (size_t)r * DM + s * 8);
        }
#pragma unroll
        for (int p = tid; p < 1024; p += 256) {
            int d = p >> 4, s = p & 15;
            *(uint4*)&sV[d * 136 + s * 8] =
                *(const uint4*)(g_vt + vbase + (size_t)d * NN + s * 8);
        }
        __syncthreads();

        // ---- two 64-wide chunks per tile ----
#pragma unroll
        for (int hf = 0; hf < 2; hf++) {
            // S = Q K^T  (16 x 64 per warp per chunk)
            float sacc[8][4];
#pragma unroll
            for (int j = 0; j < 8; j++) {
                sacc[j][0] = 0.f; sacc[j][1] = 0.f; sacc[j][2] = 0.f; sacc[j][3] = 0.f;
            }
#pragma unroll
            for (int j = 0; j < 8; j++) {
                int rb = (hf * 64 + j * 8 + g) * 72 + t * 2;
#pragma unroll
                for (int c4 = 0; c4 < 4; c4++) {
                    unsigned b0 = *(const unsigned*)&sK[rb + c4 * 16];
                    unsigned b1 = *(const unsigned*)&sK[rb + c4 * 16 + 8];
                    mma16816(sacc[j], qa[c4][0], qa[c4][1], qa[c4][2], qa[c4][3], b0, b1);
                }
            }
#pragma unroll
            for (int j = 0; j < 8; j++) {
                sacc[j][0] *= sc; sacc[j][1] *= sc; sacc[j][2] *= sc; sacc[j][3] *= sc;
            }

            // cold path: per-element mask for partial tiles
            if (flag == 2) {
                const int* mb = mask + (size_t)b * NN * NN;
                int gr0 = qb * 128 + w * 16 + g;
                int gc0 = kb * 128 + hf * 64 + t * 2;
#pragma unroll
                for (int j = 0; j < 8; j++) {
                    int gc = gc0 + j * 8;
                    if (mb[(size_t)gr0 * NN + gc] == 0)           sacc[j][0] = -1e30f;
                    if (mb[(size_t)gr0 * NN + gc + 1] == 0)       sacc[j][1] = -1e30f;
                    if (mb[(size_t)(gr0 + 8) * NN + gc] == 0)     sacc[j][2] = -1e30f;
                    if (mb[(size_t)(gr0 + 8) * NN + gc + 1] == 0) sacc[j][3] = -1e30f;
                }
            }

            // online softmax: row max, rescale, exp, row sum
            float mx0 = -1e30f, mx1 = -1e30f;
#pragma unroll
            for (int j = 0; j < 8; j++) {
                mx0 = fmaxf(mx0, fmaxf(sacc[j][0], sacc[j][1]));
                mx1 = fmaxf(mx1, fmaxf(sacc[j][2], sacc[j][3]));
            }
            mx0 = fmaxf(mx0, __shfl_xor_sync(0xffffffffu, mx0, 1));
            mx0 = fmaxf(mx0, __shfl_xor_sync(0xffffffffu, mx0, 2));
            mx1 = fmaxf(mx1, __shfl_xor_sync(0xffffffffu, mx1, 1));
            mx1 = fmaxf(mx1, __shfl_xor_sync(0xffffffffu, mx1, 2));

            float mn0 = fmaxf(m0, mx0), mn1 = fmaxf(m1, mx1);
            float al0 = __expf(m0 - mn0), al1 = __expf(m1 - mn1);
            m0 = mn0; m1 = mn1;

            float rs0 = 0.f, rs1 = 0.f;
            unsigned ph[16];
#pragma unroll
            for (int j = 0; j < 8; j++) {
                float p0 = (sacc[j][0] > -1e29f) ? __expf(sacc[j][0] - mn0) : 0.f;
                float p1 = (sacc[j][1] > -1e29f) ? __expf(sacc[j][1] - mn0) : 0.f;
                float p2 = (sacc[j][2] > -1e29f) ? __expf(sacc[j][2] - mn1) : 0.f;
                float p3 = (sacc[j][3] > -1e29f) ? __expf(sacc[j][3] - mn1) : 0.f;
                rs0 += p0 + p1;
                rs1 += p2 + p3;
                ph[2 * j]     = pack_h2(p0, p1);
                ph[2 * j + 1] = pack_h2(p2, p3);
            }
            rs0 += __shfl_xor_sync(0xffffffffu, rs0, 1);
            rs0 += __shfl_xor_sync(0xffffffffu, rs0, 2);
            rs1 += __shfl_xor_sync(0xffffffffu, rs1, 1);
            rs1 += __shfl_xor_sync(0xffffffffu, rs1, 2);
            l0 = al0 * l0 + rs0;
            l1 = al1 * l1 + rs1;

#pragma unroll
            for (int j = 0; j < 8; j++) {
                oacc[j][0] *= al0; oacc[j][1] *= al0;
                oacc[j][2] *= al1; oacc[j][3] *= al1;
            }

            // O += P V   (A = P 16x64, B = V 64x64 from transposed smem)
#pragma unroll
            for (int kc = 0; kc < 4; kc++) {
                unsigned a0 = ph[4 * kc], a1 = ph[4 * kc + 1];
                unsigned a2 = ph[4 * kc + 2], a3 = ph[4 * kc + 3];
#pragma unroll
                for (int j2 = 0; j2 < 8; j2++) {
                    int vb = (j2 * 8 + g) * 136 + hf * 64 + kc * 16 + t * 2;
                    unsigned b0 = *(const unsigned*)&sV[vb];
                    unsigned b1 = *(const unsigned*)&sV[vb + 8];
                    mma16816(oacc[j2], a0, a1, a2, a3, b0, b1);
                }
            }
        }
        __syncthreads();
    }

    // ---- epilogue: normalize, write O, l, m ----
    float inv0 = (l0 > 0.f) ? (1.f / l0) : 0.f;
    float inv1 = (l1 > 0.f) ? (1.f / l1) : 0.f;
    float* ob = out + ((size_t)b * NN + (size_t)qb * 128 + w * 16) * DM + h * DK;
#pragma unroll
    for (int j2 = 0; j2 < 8; j2++) {
        float2 v0 = make_float2(oacc[j2][0] * inv0, oacc[j2][1] * inv0);
        float2 v1 = make_float2(oacc[j2][2] * inv1, oacc[j2][3] * inv1);
        *(float2*)(ob + (size_t)g * DM + j2 * 8 + t * 2) = v0;
        *(float2*)(ob + (size_t)(g + 8) * DM + j2 * 8 + t * 2) = v1;
    }
    if (t == 0) {
        size_t lmb = ((size_t)(b * HH + h)) * NN + qb * 128 + w * 16;
        float* lout = out + (size_t)BB * NN * DM;
        float* mout = lout + (size_t)BB * HH * NN;
        const float NINF = __int_as_float(0xff800000);
        lout[lmb + g]     = l0;
        lout[lmb + g + 8] = l1;
        mout[lmb + g]     = (l0 > 0.f) ? m0 : NINF;
        mout[lmb + g + 8] = (l1 > 0.f) ? m1 : NINF;
    }
}

extern "C" void kernel_launch(void* const* d_in, const int* in_sizes, int n_in,
                              void* d_out, int out_size) {
    const float* q    = (const float*)d_in[0];
    const float* k    = (const float*)d_in[1];
    const float* v    = (const float*)d_in[2];
    const float* tau  = (const float*)d_in[3];
    const int*   mask = (const int*)d_in[4];
    const int*   bsm  = (const int*)d_in[5];
    float* out = (float*)d_out;

    convert_qk_kernel<<<2048, 256>>>(q, k);
    vtrans_kernel<<<dim3(NN / 32, HH * 2, BB), dim3(32, 32)>>>(v);
    prepass_kernel<<<dim3(TBB, TBB, BB), 256>>>(mask, bsm);
    attn_kernel<<<dim3(HH, TBB, BB), 256>>>(tau, mask, out);
}

// round 9
// speedup vs baseline: 1.1560x; 1.1560x over previous
#include <cuda_runtime.h>
#include <cuda_fp16.h>
#include <cstdint>

#define BB  2
#define NN  2048
#define DM  1024
#define HH  16
#define DK  64
#define TBB 16

// ---------------------------------------------------------------------------
// Device scratch (static; no allocation)
// ---------------------------------------------------------------------------
__device__ int    g_flags[BB * TBB * TBB];         // 0=skip, 1=full, 2=partial
__device__ __half g_qh[(size_t)BB * NN * DM];      // Q fp16, input layout
__device__ __half g_kh[(size_t)BB * NN * DM];      // K fp16, input layout
__device__ __half g_vt[(size_t)BB * HH * DK * NN]; // V fp16 transposed [b][h][d][n]

// ---------------------------------------------------------------------------
// cp.async helpers
// ---------------------------------------------------------------------------
__device__ __forceinline__ void cp16(void* smem_dst, const void* gmem_src) {
    unsigned saddr = (unsigned)__cvta_generic_to_shared(smem_dst);
    asm volatile("cp.async.ca.shared.global [%0], [%1], 16;\n"
                 :: "r"(saddr), "l"(gmem_src) : "memory");
}
__device__ __forceinline__ void cp_wait_all() {
    asm volatile("cp.async.commit_group;\ncp.async.wait_group 0;\n" ::: "memory");
}

// ---------------------------------------------------------------------------
// Prepass 1: convert Q and K to fp16 (layout-preserving)
// ---------------------------------------------------------------------------
__global__ void __launch_bounds__(256) convert_qk_kernel(const float* __restrict__ q,
                                                         const float* __restrict__ k) {
    const size_t total = (size_t)BB * NN * DM / 4;
    __half2* qo = reinterpret_cast<__half2*>(g_qh);
    __half2* ko = reinterpret_cast<__half2*>(g_kh);
    const float4* qi = reinterpret_cast<const float4*>(q);
    const float4* ki = reinterpret_cast<const float4*>(k);
    for (size_t i = (size_t)blockIdx.x * blockDim.x + threadIdx.x; i < total;
         i += (size_t)gridDim.x * blockDim.x) {
        float4 fq = qi[i];
        qo[2 * i]     = __floats2half2_rn(fq.x, fq.y);
        qo[2 * i + 1] = __floats2half2_rn(fq.z, fq.w);
        float4 fk = ki[i];
        ko[2 * i]     = __floats2half2_rn(fk.x, fk.y);
        ko[2 * i + 1] = __floats2half2_rn(fk.z, fk.w);
    }
}

// ---------------------------------------------------------------------------
// Prepass 2: V -> fp16 transposed per head: g_vt[b][h][d][n] = V[b][n][h*64+d]
// ---------------------------------------------------------------------------
__global__ void __launch_bounds__(1024) vtrans_kernel(const float* __restrict__ v) {
    __shared__ float tile[32][33];
    const int tx = threadIdx.x, ty = threadIdx.y;
    const int n0 = blockIdx.x * 32;
    const int h  = blockIdx.y >> 1;
    const int d0 = (blockIdx.y & 1) * 32;
    const int b  = blockIdx.z;
    tile[tx][ty] = v[((size_t)(b * NN + n0 + ty)) * DM + h * DK + d0 + tx];
    __syncthreads();
    g_vt[((size_t)((b * HH + h) * DK + d0 + ty)) * NN + n0 + tx] =
        __float2half_rn(tile[ty][tx]);
}

// ---------------------------------------------------------------------------
// Prepass 3: compress token mask x block-sparse mask into per-tile flags.
// int4-vectorized; reads the 33.5MB mask exactly once.
// ---------------------------------------------------------------------------
__global__ void __launch_bounds__(256) prepass_kernel(const int* __restrict__ mask,
                                                      const int* __restrict__ bsm) {
    int kb = blockIdx.x, qb = blockIdx.y, b = blockIdx.z;
    int t = threadIdx.x;
    int allv = 1, anyv = 0;
    const int* base = mask + ((size_t)b * NN + (size_t)qb * 128) * NN + (size_t)kb * 128;
    for (int i = t; i < 4096; i += 256) {
        int r = i >> 5, c4 = i & 31;
        int4 m4 = *(const int4*)(base + (size_t)r * NN + c4 * 4);
        int nz_all = (m4.x != 0) & (m4.y != 0) & (m4.z != 0) & (m4.w != 0);
        int nz_any = (m4.x != 0) | (m4.y != 0) | (m4.z != 0) | (m4.w != 0);
        allv &= nz_all;
        anyv |= nz_any;
    }
    for (int off = 16; off; off >>= 1) {
        allv &= __shfl_xor_sync(0xffffffffu, allv, off);
        anyv |= __shfl_xor_sync(0xffffffffu, anyv, off);
    }
    __shared__ int s_all[8], s_any[8];
    int w = t >> 5;
    if ((t & 31) == 0) { s_all[w] = allv; s_any[w] = anyv; }
    __syncthreads();
    if (t == 0) {
        int A = 1, O = 0;
        for (int i = 0; i < 8; i++) { A &= s_all[i]; O |= s_any[i]; }
        int f = 0;
        if (bsm[qb * TBB + kb] != 0 && O) f = A ? 1 : 2;
        g_flags[(b * TBB + qb) * TBB + kb] = f;
    }
}

// ---------------------------------------------------------------------------
// mma.sync m16n8k16 row.col f32.f16.f16.f32
// ---------------------------------------------------------------------------
__device__ __forceinline__ void mma16816(float c[4],
                                         unsigned a0, unsigned a1, unsigned a2, unsigned a3,
                                         unsigned b0, unsigned b1) {
    asm volatile(
        "mma.sync.aligned.m16n8k16.row.col.f32.f16.f16.f32 "
        "{%0,%1,%2,%3}, {%4,%5,%6,%7}, {%8,%9}, {%0,%1,%2,%3};\n"
        : "+f"(c[0]), "+f"(c[1]), "+f"(c[2]), "+f"(c[3])
        : "r"(a0), "r"(a1), "r"(a2), "r"(a3), "r"(b0), "r"(b1));
}

__device__ __forceinline__ float pack_h2_as_f(float a, float b) {
    __half2 h = __floats2half2_rn(a, b);
    return __uint_as_float(*reinterpret_cast<unsigned*>(&h));
}

// ---------------------------------------------------------------------------
// Flash attention. Grid (H, TB, B), 8 warps/CTA, 2 CTAs/SM (128-reg cap).
// Each 128-wide K tile processed as two 64-wide online-softmax chunks.
// Packed-P reuses the dead sacc registers to stay under the reg cap.
// ---------------------------------------------------------------------------
__global__ void __launch_bounds__(256, 2) attn_kernel(const float* __restrict__ taup,
                                                      const int* __restrict__ mask,
                                                      float* __restrict__ out) {
    __shared__ __half sK[128 * 72];   // K tile [kk][d], stride 72 (also Q staging)
    __shared__ __half sV[64 * 136];   // V tile transposed [d][kk], stride 136

    const int h = blockIdx.x, qb = blockIdx.y, b = blockIdx.z;
    const int tid = threadIdx.x;
    const int w = tid >> 5, lane = tid & 31;
    const int g = lane >> 2, t = lane & 3;

    const float sc = __ldg(taup) * 0.125f;   // tau / sqrt(64)

    // ---- stage Q tile through sK, build A fragments ----
    {
        const size_t qbase = ((size_t)(b * NN + qb * 128)) * DM + h * DK;
#pragma unroll
        for (int p = tid; p < 1024; p += 256) {
            int r = p >> 3, s = p & 7;
            cp16(&sK[r * 72 + s * 8], g_qh + qbase + (size_t)r * DM + s * 8);
        }
        cp_wait_all();
    }
    __syncthreads();
    unsigned qa[4][4];
    {
        int r0 = w * 16 + g;
#pragma unroll
        for (int c4 = 0; c4 < 4; c4++) {
            int cb = c4 * 16 + t * 2;
            qa[c4][0] = *(const unsigned*)&sK[r0 * 72 + cb];
            qa[c4][1] = *(const unsigned*)&sK[(r0 + 8) * 72 + cb];
            qa[c4][2] = *(const unsigned*)&sK[r0 * 72 + cb + 8];
            qa[c4][3] = *(const unsigned*)&sK[(r0 + 8) * 72 + cb + 8];
        }
    }
    __syncthreads();

    float oacc[8][4];
#pragma unroll
    for (int j = 0; j < 8; j++) {
        oacc[j][0] = 0.f; oacc[j][1] = 0.f; oacc[j][2] = 0.f; oacc[j][3] = 0.f;
    }
    float m0 = -1e30f, m1 = -1e30f, l0 = 0.f, l1 = 0.f;

    const int frow = (b * TBB + qb) * TBB;
    const size_t kbase0 = ((size_t)(b * NN)) * DM + h * DK;
    const size_t vbase0 = ((size_t)((b * HH + h) * DK)) * NN;

    for (int kb = 0; kb < TBB; kb++) {
        const int flag = g_flags[frow + kb];
        if (flag == 0) continue;

        // ---- cp.async fill: K tile + transposed V tile ----
        const size_t kbase = kbase0 + (size_t)kb * 128 * DM;
        const size_t vbase = vbase0 + (size_t)kb * 128;
#pragma unroll
        for (int p = tid; p < 1024; p += 256) {
            int r = p >> 3, s = p & 7;
            cp16(&sK[r * 72 + s * 8], g_kh + kbase + (size_t)r * DM + s * 8);
        }
#pragma unroll
        for (int p = tid; p < 1024; p += 256) {
            int d = p >> 4, s = p & 15;
            cp16(&sV[d * 136 + s * 8], g_vt + vbase + (size_t)d * NN + s * 8);
        }
        cp_wait_all();
        __syncthreads();

        // ---- two 64-wide chunks per tile ----
#pragma unroll
        for (int hf = 0; hf < 2; hf++) {
            // S = Q K^T  (16 x 64 per warp per chunk)
            float sacc[8][4];
#pragma unroll
            for (int j = 0; j < 8; j++) {
                sacc[j][0] = 0.f; sacc[j][1] = 0.f; sacc[j][2] = 0.f; sacc[j][3] = 0.f;
            }
#pragma unroll
            for (int j = 0; j < 8; j++) {
                int rb = (hf * 64 + j * 8 + g) * 72 + t * 2;
#pragma unroll
                for (int c4 = 0; c4 < 4; c4++) {
                    unsigned b0 = *(const unsigned*)&sK[rb + c4 * 16];
                    unsigned b1 = *(const unsigned*)&sK[rb + c4 * 16 + 8];
                    mma16816(sacc[j], qa[c4][0], qa[c4][1], qa[c4][2], qa[c4][3], b0, b1);
                }
            }
#pragma unroll
            for (int j = 0; j < 8; j++) {
                sacc[j][0] *= sc; sacc[j][1] *= sc; sacc[j][2] *= sc; sacc[j][3] *= sc;
            }

            // cold path: per-element mask for partial tiles
            if (flag == 2) {
                const int* mb = mask + (size_t)b * NN * NN;
                int gr0 = qb * 128 + w * 16 + g;
                int gc0 = kb * 128 + hf * 64 + t * 2;
#pragma unroll
                for (int j = 0; j < 8; j++) {
                    int gc = gc0 + j * 8;
                    if (mb[(size_t)gr0 * NN + gc] == 0)           sacc[j][0] = -1e30f;
                    if (mb[(size_t)gr0 * NN + gc + 1] == 0)       sacc[j][1] = -1e30f;
                    if (mb[(size_t)(gr0 + 8) * NN + gc] == 0)     sacc[j][2] = -1e30f;
                    if (mb[(size_t)(gr0 + 8) * NN + gc + 1] == 0) sacc[j][3] = -1e30f;
                }
            }

            // online softmax: row max, rescale, exp, row sum
            float mx0 = -1e30f, mx1 = -1e30f;
#pragma unroll
            for (int j = 0; j < 8; j++) {
                mx0 = fmaxf(mx0, fmaxf(sacc[j][0], sacc[j][1]));
                mx1 = fmaxf(mx1, fmaxf(sacc[j][2], sacc[j][3]));
            }
            mx0 = fmaxf(mx0, __shfl_xor_sync(0xffffffffu, mx0, 1));
            mx0 = fmaxf(mx0, __shfl_xor_sync(0xffffffffu, mx0, 2));
            mx1 = fmaxf(mx1, __shfl_xor_sync(0xffffffffu, mx1, 1));
            mx1 = fmaxf(mx1, __shfl_xor_sync(0xffffffffu, mx1, 2));

            float mn0 = fmaxf(m0, mx0), mn1 = fmaxf(m1, mx1);
            float al0 = __expf(m0 - mn0), al1 = __expf(m1 - mn1);
            m0 = mn0; m1 = mn1;

            // exp + pack P into the dead sacc registers:
            //   sacc[j][0] <- half2(p0,p1) bits, sacc[j][1] <- half2(p2,p3) bits
            float rs0 = 0.f, rs1 = 0.f;
#pragma unroll
            for (int j = 0; j < 8; j++) {
                float p0 = (sacc[j][0] > -1e29f) ? __expf(sacc[j][0] - mn0) : 0.f;
                float p1 = (sacc[j][1] > -1e29f) ? __expf(sacc[j][1] - mn0) : 0.f;
                float p2 = (sacc[j][2] > -1e29f) ? __expf(sacc[j][2] - mn1) : 0.f;
                float p3 = (sacc[j][3] > -1e29f) ? __expf(sacc[j][3] - mn1) : 0.f;
                rs0 += p0 + p1;
                rs1 += p2 + p3;
                sacc[j][0] = pack_h2_as_f(p0, p1);
                sacc[j][1] = pack_h2_as_f(p2, p3);
            }
            rs0 += __shfl_xor_sync(0xffffffffu, rs0, 1);
            rs0 += __shfl_xor_sync(0xffffffffu, rs0, 2);
            rs1 += __shfl_xor_sync(0xffffffffu, rs1, 1);
            rs1 += __shfl_xor_sync(0xffffffffu, rs1, 2);
            l0 = al0 * l0 + rs0;
            l1 = al1 * l1 + rs1;

#pragma unroll
            for (int j = 0; j < 8; j++) {
                oacc[j][0] *= al0; oacc[j][1] *= al0;
                oacc[j][2] *= al1; oacc[j][3] *= al1;
            }

            // O += P V   (A fragments read back from packed sacc)
#pragma unroll
            for (int kc = 0; kc < 4; kc++) {
                unsigned a0 = __float_as_uint(sacc[2 * kc][0]);
                unsigned a1 = __float_as_uint(sacc[2 * kc][1]);
                unsigned a2 = __float_as_uint(sacc[2 * kc + 1][0]);
                unsigned a3 = __float_as_uint(sacc[2 * kc + 1][1]);
#pragma unroll
                for (int j2 = 0; j2 < 8; j2++) {
                    int vb = (j2 * 8 + g) * 136 + hf * 64 + kc * 16 + t * 2;
                    unsigned b0 = *(const unsigned*)&sV[vb];
                    unsigned b1 = *(const unsigned*)&sV[vb + 8];
                    mma16816(oacc[j2], a0, a1, a2, a3, b0, b1);
                }
            }
        }
        __syncthreads();
    }

    // ---- epilogue: normalize, write O, l, m ----
    float inv0 = (l0 > 0.f) ? (1.f / l0) : 0.f;
    float inv1 = (l1 > 0.f) ? (1.f / l1) : 0.f;
    float* ob = out + ((size_t)b * NN + (size_t)qb * 128 + w * 16) * DM + h * DK;
#pragma unroll
    for (int j2 = 0; j2 < 8; j2++) {
        float2 v0 = make_float2(oacc[j2][0] * inv0, oacc[j2][1] * inv0);
        float2 v1 = make_float2(oacc[j2][2] * inv1, oacc[j2][3] * inv1);
        *(float2*)(ob + (size_t)g * DM + j2 * 8 + t * 2) = v0;
        *(float2*)(ob + (size_t)(g + 8) * DM + j2 * 8 + t * 2) = v1;
    }
    if (t == 0) {
        size_t lmb = ((size_t)(b * HH + h)) * NN + qb * 128 + w * 16;
        float* lout = out + (size_t)BB * NN * DM;
        float* mout = lout + (size_t)BB * HH * NN;
        const float NINF = __int_as_float(0xff800000);
        lout[lmb + g]     = l0;
        lout[lmb + g + 8] = l1;
        mout[lmb + g]     = (l0 > 0.f) ? m0 : NINF;
        mout[lmb + g + 8] = (l1 > 0.f) ? m1 : NINF;
    }
}

extern "C" void kernel_launch(void* const* d_in, const int* in_sizes, int n_in,
                              void* d_out, int out_size) {
    const float* q    = (const float*)d_in[0];
    const float* k    = (const float*)d_in[1];
    const float* v    = (const float*)d_in[2];
    const float* tau  = (const float*)d_in[3];
    const int*   mask = (const int*)d_in[4];
    const int*   bsm  = (const int*)d_in[5];
    float* out = (float*)d_out;

    convert_qk_kernel<<<1024, 256>>>(q, k);
    vtrans_kernel<<<dim3(NN / 32, HH * 2, BB), dim3(32, 32)>>>(v);
    prepass_kernel<<<dim3(TBB, TBB, BB), 256>>>(mask, bsm);
    attn_kernel<<<dim3(HH, TBB, BB), 256>>>(tau, mask, out);
}

// round 10
// speedup vs baseline: 1.2785x; 1.1060x over previous
#include <cuda_runtime.h>
#include <cuda_fp16.h>
#include <cstdint>

#define BB  2
#define NN  2048
#define DM  1024
#define HH  16
#define DK  64
#define TBB 16

// ---------------------------------------------------------------------------
// Device scratch (static; no allocation)
// ---------------------------------------------------------------------------
__device__ int    g_flags[BB * TBB * TBB];         // 0=skip, 1=full, 2=partial
__device__ __half g_qh[(size_t)BB * NN * DM];      // Q * tau/sqrt(dk), fp16
__device__ __half g_kh[(size_t)BB * NN * DM];      // K fp16, input layout
__device__ __half g_vt[(size_t)BB * HH * DK * NN]; // V fp16 transposed [b][h][d][n]

// ---------------------------------------------------------------------------
// cp.async / ldmatrix helpers
// ---------------------------------------------------------------------------
__device__ __forceinline__ void cp16(void* smem_dst, const void* gmem_src) {
    unsigned saddr = (unsigned)__cvta_generic_to_shared(smem_dst);
    asm volatile("cp.async.ca.shared.global [%0], [%1], 16;\n"
                 :: "r"(saddr), "l"(gmem_src) : "memory");
}
__device__ __forceinline__ void cp_wait_all() {
    asm volatile("cp.async.commit_group;\ncp.async.wait_group 0;\n" ::: "memory");
}
__device__ __forceinline__ void ldsm_x4(unsigned& r0, unsigned& r1,
                                        unsigned& r2, unsigned& r3, unsigned saddr) {
    asm volatile("ldmatrix.sync.aligned.m8n8.x4.shared.b16 {%0,%1,%2,%3}, [%4];\n"
                 : "=r"(r0), "=r"(r1), "=r"(r2), "=r"(r3) : "r"(saddr));
}

// ---------------------------------------------------------------------------
// Prepass 1: Q -> fp16 * (tau/sqrt(dk)), K -> fp16 (layout-preserving)
// ---------------------------------------------------------------------------
__global__ void __launch_bounds__(256) convert_qk_kernel(const float* __restrict__ q,
                                                         const float* __restrict__ k,
                                                         const float* __restrict__ taup) {
    const float sc = __ldg(taup) * 0.125f;
    const size_t total = (size_t)BB * NN * DM / 4;
    __half2* qo = reinterpret_cast<__half2*>(g_qh);
    __half2* ko = reinterpret_cast<__half2*>(g_kh);
    const float4* qi = reinterpret_cast<const float4*>(q);
    const float4* ki = reinterpret_cast<const float4*>(k);
    for (size_t i = (size_t)blockIdx.x * blockDim.x + threadIdx.x; i < total;
         i += (size_t)gridDim.x * blockDim.x) {
        float4 fq = qi[i];
        qo[2 * i]     = __floats2half2_rn(fq.x * sc, fq.y * sc);
        qo[2 * i + 1] = __floats2half2_rn(fq.z * sc, fq.w * sc);
        float4 fk = ki[i];
        ko[2 * i]     = __floats2half2_rn(fk.x, fk.y);
        ko[2 * i + 1] = __floats2half2_rn(fk.z, fk.w);
    }
}

// ---------------------------------------------------------------------------
// Prepass 2: V -> fp16 transposed per head: g_vt[b][h][d][n] = V[b][n][h*64+d]
// ---------------------------------------------------------------------------
__global__ void __launch_bounds__(1024) vtrans_kernel(const float* __restrict__ v) {
    __shared__ float tile[32][33];
    const int tx = threadIdx.x, ty = threadIdx.y;
    const int n0 = blockIdx.x * 32;
    const int h  = blockIdx.y >> 1;
    const int d0 = (blockIdx.y & 1) * 32;
    const int b  = blockIdx.z;
    tile[tx][ty] = v[((size_t)(b * NN + n0 + ty)) * DM + h * DK + d0 + tx];
    __syncthreads();
    g_vt[((size_t)((b * HH + h) * DK + d0 + ty)) * NN + n0 + tx] =
        __float2half_rn(tile[ty][tx]);
}

// ---------------------------------------------------------------------------
// Prepass 3: compress token mask x block-sparse mask into per-tile flags.
// ---------------------------------------------------------------------------
__global__ void __launch_bounds__(256) prepass_kernel(const int* __restrict__ mask,
                                                      const int* __restrict__ bsm) {
    int kb = blockIdx.x, qb = blockIdx.y, b = blockIdx.z;
    int t = threadIdx.x;
    int allv = 1, anyv = 0;
    const int* base = mask + ((size_t)b * NN + (size_t)qb * 128) * NN + (size_t)kb * 128;
    for (int i = t; i < 4096; i += 256) {
        int r = i >> 5, c4 = i & 31;
        int4 m4 = *(const int4*)(base + (size_t)r * NN + c4 * 4);
        allv &= (m4.x != 0) & (m4.y != 0) & (m4.z != 0) & (m4.w != 0);
        anyv |= (m4.x != 0) | (m4.y != 0) | (m4.z != 0) | (m4.w != 0);
    }
    for (int off = 16; off; off >>= 1) {
        allv &= __shfl_xor_sync(0xffffffffu, allv, off);
        anyv |= __shfl_xor_sync(0xffffffffu, anyv, off);
    }
    __shared__ int s_all[8], s_any[8];
    int w = t >> 5;
    if ((t & 31) == 0) { s_all[w] = allv; s_any[w] = anyv; }
    __syncthreads();
    if (t == 0) {
        int A = 1, O = 0;
        for (int i = 0; i < 8; i++) { A &= s_all[i]; O |= s_any[i]; }
        int f = 0;
        if (bsm[qb * TBB + kb] != 0 && O) f = A ? 1 : 2;
        g_flags[(b * TBB + qb) * TBB + kb] = f;
    }
}

// ---------------------------------------------------------------------------
// mma.sync m16n8k16 row.col f32.f16.f16.f32
// ---------------------------------------------------------------------------
__device__ __forceinline__ void mma16816(float c[4],
                                         unsigned a0, unsigned a1, unsigned a2, unsigned a3,
                                         unsigned b0, unsigned b1) {
    asm volatile(
        "mma.sync.aligned.m16n8k16.row.col.f32.f16.f16.f32 "
        "{%0,%1,%2,%3}, {%4,%5,%6,%7}, {%8,%9}, {%0,%1,%2,%3};\n"
        : "+f"(c[0]), "+f"(c[1]), "+f"(c[2]), "+f"(c[3])
        : "r"(a0), "r"(a1), "r"(a2), "r"(a3), "r"(b0), "r"(b1));
}

__device__ __forceinline__ float pack_h2_as_f(float a, float b) {
    __half2 h = __floats2half2_rn(a, b);
    return __uint_as_float(*reinterpret_cast<unsigned*>(&h));
}

// ---------------------------------------------------------------------------
// Flash attention. Grid (H, TB, B), 8 warps/CTA, 2 CTAs/SM.
// LDSM B-fragments; scale folded into Q prepass; guarded softmax only for
// partial tiles. 128-wide K tiles as two 64-wide online-softmax chunks.
// ---------------------------------------------------------------------------
__global__ void __launch_bounds__(256, 2) attn_kernel(const int* __restrict__ mask,
                                                      float* __restrict__ out) {
    __shared__ __half sK[128 * 72];   // K tile [token][d], stride 72 (also Q staging)
    __shared__ __half sV[64 * 136];   // V tile transposed [d][token], stride 136

    const int h = blockIdx.x, qb = blockIdx.y, b = blockIdx.z;
    const int tid = threadIdx.x;
    const int w = tid >> 5, lane = tid & 31;
    const int g = lane >> 2, t = lane & 3;
    const int l7 = lane & 7, l3 = lane >> 3;   // ldmatrix row / matrix index

    // ---- stage Q tile (pre-scaled fp16) through sK, build A fragments ----
    {
        const size_t qbase = ((size_t)(b * NN + qb * 128)) * DM + h * DK;
#pragma unroll
        for (int p = tid; p < 1024; p += 256) {
            int r = p >> 3, s = p & 7;
            cp16(&sK[r * 72 + s * 8], g_qh + qbase + (size_t)r * DM + s * 8);
        }
        cp_wait_all();
    }
    __syncthreads();
    unsigned qa[4][4];
    {
        int r0 = w * 16 + g;
#pragma unroll
        for (int c4 = 0; c4 < 4; c4++) {
            int cb = c4 * 16 + t * 2;
            qa[c4][0] = *(const unsigned*)&sK[r0 * 72 + cb];
            qa[c4][1] = *(const unsigned*)&sK[(r0 + 8) * 72 + cb];
            qa[c4][2] = *(const unsigned*)&sK[r0 * 72 + cb + 8];
            qa[c4][3] = *(const unsigned*)&sK[(r0 + 8) * 72 + cb + 8];
        }
    }
    __syncthreads();

    const unsigned sK_u = (unsigned)__cvta_generic_to_shared(sK);
    const unsigned sV_u = (unsigned)__cvta_generic_to_shared(sV);

    float oacc[8][4];
#pragma unroll
    for (int j = 0; j < 8; j++) {
        oacc[j][0] = 0.f; oacc[j][1] = 0.f; oacc[j][2] = 0.f; oacc[j][3] = 0.f;
    }
    float m0 = -1e30f, m1 = -1e30f, l0 = 0.f, l1 = 0.f;

    const int frow = (b * TBB + qb) * TBB;
    const size_t kbase0 = ((size_t)(b * NN)) * DM + h * DK;
    const size_t vbase0 = ((size_t)((b * HH + h) * DK)) * NN;

    for (int kb = 0; kb < TBB; kb++) {
        const int flag = g_flags[frow + kb];
        if (flag == 0) continue;

        // ---- cp.async fill: K tile + transposed V tile ----
        const size_t kbase = kbase0 + (size_t)kb * 128 * DM;
        const size_t vbase = vbase0 + (size_t)kb * 128;
#pragma unroll
        for (int p = tid; p < 1024; p += 256) {
            int r = p >> 3, s = p & 7;
            cp16(&sK[r * 72 + s * 8], g_kh + kbase + (size_t)r * DM + s * 8);
        }
#pragma unroll
        for (int p = tid; p < 1024; p += 256) {
            int d = p >> 4, s = p & 15;
            cp16(&sV[d * 136 + s * 8], g_vt + vbase + (size_t)d * NN + s * 8);
        }
        cp_wait_all();
        __syncthreads();

        // ---- two 64-wide chunks per tile ----
#pragma unroll
        for (int hf = 0; hf < 2; hf++) {
            // S = Q K^T  (16 x 64 per warp per chunk), B via ldmatrix.x4
            float sacc[8][4];
#pragma unroll
            for (int j = 0; j < 8; j++) {
                sacc[j][0] = 0.f; sacc[j][1] = 0.f; sacc[j][2] = 0.f; sacc[j][3] = 0.f;
            }
#pragma unroll
            for (int j = 0; j < 8; j++) {
                unsigned addr = sK_u + ((hf * 64 + j * 8 + l7) * 72) * 2 + l3 * 16;
                unsigned b0, b1, b2, b3, b4, b5, b6, b7;
                ldsm_x4(b0, b1, b2, b3, addr);        // d cols 0..31  (c4=0,1)
                ldsm_x4(b4, b5, b6, b7, addr + 64);   // d cols 32..63 (c4=2,3)
                mma16816(sacc[j], qa[0][0], qa[0][1], qa[0][2], qa[0][3], b0, b1);
                mma16816(sacc[j], qa[1][0], qa[1][1], qa[1][2], qa[1][3], b2, b3);
                mma16816(sacc[j], qa[2][0], qa[2][1], qa[2][2], qa[2][3], b4, b5);
                mma16816(sacc[j], qa[3][0], qa[3][1], qa[3][2], qa[3][3], b6, b7);
            }

            // cold path: per-element mask for partial tiles
            if (flag == 2) {
                const int* mb = mask + (size_t)b * NN * NN;
                int gr0 = qb * 128 + w * 16 + g;
                int gc0 = kb * 128 + hf * 64 + t * 2;
#pragma unroll
                for (int j = 0; j < 8; j++) {
                    int gc = gc0 + j * 8;
                    if (mb[(size_t)gr0 * NN + gc] == 0)           sacc[j][0] = -1e30f;
                    if (mb[(size_t)gr0 * NN + gc + 1] == 0)       sacc[j][1] = -1e30f;
                    if (mb[(size_t)(gr0 + 8) * NN + gc] == 0)     sacc[j][2] = -1e30f;
                    if (mb[(size_t)(gr0 + 8) * NN + gc + 1] == 0) sacc[j][3] = -1e30f;
                }
            }

            // online softmax: row max, rescale, exp, row sum
            float mx0 = -1e30f, mx1 = -1e30f;
#pragma unroll
            for (int j = 0; j < 8; j++) {
                mx0 = fmaxf(mx0, fmaxf(sacc[j][0], sacc[j][1]));
                mx1 = fmaxf(mx1, fmaxf(sacc[j][2], sacc[j][3]));
            }
            mx0 = fmaxf(mx0, __shfl_xor_sync(0xffffffffu, mx0, 1));
            mx0 = fmaxf(mx0, __shfl_xor_sync(0xffffffffu, mx0, 2));
            mx1 = fmaxf(mx1, __shfl_xor_sync(0xffffffffu, mx1, 1));
            mx1 = fmaxf(mx1, __shfl_xor_sync(0xffffffffu, mx1, 2));

            float mn0 = fmaxf(m0, mx0), mn1 = fmaxf(m1, mx1);
            float al0 = __expf(m0 - mn0), al1 = __expf(m1 - mn1);
            m0 = mn0; m1 = mn1;

            // exp + pack P into dead sacc regs:
            //   sacc[j][0] <- half2(p0,p1) bits, sacc[j][1] <- half2(p2,p3) bits
            float rs0 = 0.f, rs1 = 0.f;
            if (flag != 2) {           // hot path: all entries valid, no guards
#pragma unroll
                for (int j = 0; j < 8; j++) {
                    float p0 = __expf(sacc[j][0] - mn0);
                    float p1 = __expf(sacc[j][1] - mn0);
                    float p2 = __expf(sacc[j][2] - mn1);
                    float p3 = __expf(sacc[j][3] - mn1);
                    rs0 += p0 + p1;
                    rs1 += p2 + p3;
                    sacc[j][0] = pack_h2_as_f(p0, p1);
                    sacc[j][1] = pack_h2_as_f(p2, p3);
                }
            } else {                   // guarded: masked entries contribute 0
#pragma unroll
                for (int j = 0; j < 8; j++) {
                    float p0 = (sacc[j][0] > -1e29f) ? __expf(sacc[j][0] - mn0) : 0.f;
                    float p1 = (sacc[j][1] > -1e29f) ? __expf(sacc[j][1] - mn0) : 0.f;
                    float p2 = (sacc[j][2] > -1e29f) ? __expf(sacc[j][2] - mn1) : 0.f;
                    float p3 = (sacc[j][3] > -1e29f) ? __expf(sacc[j][3] - mn1) : 0.f;
                    rs0 += p0 + p1;
                    rs1 += p2 + p3;
                    sacc[j][0] = pack_h2_as_f(p0, p1);
                    sacc[j][1] = pack_h2_as_f(p2, p3);
                }
            }
            rs0 += __shfl_xor_sync(0xffffffffu, rs0, 1);
            rs0 += __shfl_xor_sync(0xffffffffu, rs0, 2);
            rs1 += __shfl_xor_sync(0xffffffffu, rs1, 1);
            rs1 += __shfl_xor_sync(0xffffffffu, rs1, 2);
            l0 = al0 * l0 + rs0;
            l1 = al1 * l1 + rs1;

#pragma unroll
            for (int j = 0; j < 8; j++) {
                oacc[j][0] *= al0; oacc[j][1] *= al0;
                oacc[j][2] *= al1; oacc[j][3] *= al1;
            }

            // O += P V   (A from packed sacc, B via ldmatrix.x4)
#pragma unroll
            for (int j2 = 0; j2 < 8; j2++) {
                unsigned addr = sV_u + ((j2 * 8 + l7) * 136 + hf * 64) * 2 + l3 * 16;
                unsigned b0, b1, b2, b3, b4, b5, b6, b7;
                ldsm_x4(b0, b1, b2, b3, addr);        // tokens 0..31  (kc=0,1)
                ldsm_x4(b4, b5, b6, b7, addr + 64);   // tokens 32..63 (kc=2,3)
                mma16816(oacc[j2], __float_as_uint(sacc[0][0]), __float_as_uint(sacc[0][1]),
                         __float_as_uint(sacc[1][0]), __float_as_uint(sacc[1][1]), b0, b1);
                mma16816(oacc[j2], __float_as_uint(sacc[2][0]), __float_as_uint(sacc[2][1]),
                         __float_as_uint(sacc[3][0]), __float_as_uint(sacc[3][1]), b2, b3);
                mma16816(oacc[j2], __float_as_uint(sacc[4][0]), __float_as_uint(sacc[4][1]),
                         __float_as_uint(sacc[5][0]), __float_as_uint(sacc[5][1]), b4, b5);
                mma16816(oacc[j2], __float_as_uint(sacc[6][0]), __float_as_uint(sacc[6][1]),
                         __float_as_uint(sacc[7][0]), __float_as_uint(sacc[7][1]), b6, b7);
            }
        }
        __syncthreads();
    }

    // ---- epilogue: normalize, write O, l, m ----
    float inv0 = (l0 > 0.f) ? (1.f / l0) : 0.f;
    float inv1 = (l1 > 0.f) ? (1.f / l1) : 0.f;
    float* ob = out + ((size_t)b * NN + (size_t)qb * 128 + w * 16) * DM + h * DK;
#pragma unroll
    for (int j2 = 0; j2 < 8; j2++) {
        float2 v0 = make_float2(oacc[j2][0] * inv0, oacc[j2][1] * inv0);
        float2 v1 = make_float2(oacc[j2][2] * inv1, oacc[j2][3] * inv1);
        *(float2*)(ob + (size_t)g * DM + j2 * 8 + t * 2) = v0;
        *(float2*)(ob + (size_t)(g + 8) * DM + j2 * 8 + t * 2) = v1;
    }
    if (t == 0) {
        size_t lmb = ((size_t)(b * HH + h)) * NN + qb * 128 + w * 16;
        float* lout = out + (size_t)BB * NN * DM;
        float* mout = lout + (size_t)BB * HH * NN;
        const float NINF = __int_as_float(0xff800000);
        lout[lmb + g]     = l0;
        lout[lmb + g + 8] = l1;
        mout[lmb + g]     = (l0 > 0.f) ? m0 : NINF;
        mout[lmb + g + 8] = (l1 > 0.f) ? m1 : NINF;
    }
}

extern "C" void kernel_launch(void* const* d_in, const int* in_sizes, int n_in,
                              void* d_out, int out_size) {
    const float* q    = (const float*)d_in[0];
    const float* k    = (const float*)d_in[1];
    const float* v    = (const float*)d_in[2];
    const float* tau  = (const float*)d_in[3];
    const int*   mask = (const int*)d_in[4];
    const int*   bsm  = (const int*)d_in[5];
    float* out = (float*)d_out;

    convert_qk_kernel<<<1024, 256>>>(q, k, tau);
    vtrans_kernel<<<dim3(NN / 32, HH * 2, BB), dim3(32, 32)>>>(v);
    prepass_kernel<<<dim3(TBB, TBB, BB), 256>>>(mask, bsm);
    attn_kernel<<<dim3(HH, TBB, BB), 256>>>(mask, out);
}